// round 1
// baseline (speedup 1.0000x reference)
#include <cuda_runtime.h>
#include <cstdint>

#define NN 100000
#define EE 600000
#define ELN 200000
#define HIDN 16
#define NHEADS 4
#define NNT 8
#define NET 22
#define EDIM 16

// ---------------- device scratch ----------------
__device__ float g_h[(size_t)NN * 256];   // node projections (layer1 uses first N*64)
__device__ float g_z1[(size_t)NN * 64];   // layer1 output (post-residual, post-relu)
__device__ float g_sc[(size_t)EE * 4];    // per-edge per-head scores (post leaky-relu)
__device__ float g_ss[NN * 4];            // h . a_s per node per head
__device__ float g_sd[NN * 4];            // h . a_d per node per head
__device__ int   g_cnt[NN];
__device__ int   g_rowptr[NN + 1];
__device__ int   g_cur[NN];
__device__ int   g_eidx[EE];
__device__ float g_wae1[16 * 4], g_tae1[22 * 4];
__device__ float g_wae2[16 * 4], g_tae2[22 * 4];

// ---------------- CSR build ----------------
__global__ void k_zero_cnt() {
    int i = blockIdx.x * blockDim.x + threadIdx.x;
    if (i < NN) g_cnt[i] = 0;
}

__global__ void k_count(const int* __restrict__ ei) {
    int e = blockIdx.x * blockDim.x + threadIdx.x;
    if (e < EE) atomicAdd(&g_cnt[ei[EE + e]], 1);
}

__global__ void k_scan() {
    __shared__ int sp[1024];
    int tid = threadIdx.x;
    const int chunk = (NN + 1023) >> 10;
    int st = tid * chunk;
    int en = st + chunk; if (en > NN) en = NN;
    int s = 0;
    for (int i = st; i < en; i++) s += g_cnt[i];
    sp[tid] = s;
    __syncthreads();
    for (int o = 1; o < 1024; o <<= 1) {
        int v = (tid >= o) ? sp[tid - o] : 0;
        __syncthreads();
        sp[tid] += v;
        __syncthreads();
    }
    int b = sp[tid] - s;  // exclusive prefix for this chunk
    for (int i = st; i < en; i++) { g_rowptr[i] = b; b += g_cnt[i]; }
    if (tid == 1023) g_rowptr[NN] = sp[1023];
}

__global__ void k_initcur() {
    int i = blockIdx.x * blockDim.x + threadIdx.x;
    if (i < NN) g_cur[i] = g_rowptr[i];
}

__global__ void k_fill(const int* __restrict__ ei) {
    int e = blockIdx.x * blockDim.x + threadIdx.x;
    if (e < EE) {
        int d = ei[EE + e];
        int p = atomicAdd(&g_cur[d], 1);
        g_eidx[p] = e;
    }
}

// ---------------- small precompute: (We . a_e) and (et . a_e) tables ----------------
__global__ void k_prec(const float* __restrict__ We1, const float* __restrict__ ae1,
                       const float* __restrict__ et1,
                       const float* __restrict__ We2, const float* __restrict__ ae2,
                       const float* __restrict__ et2) {
    int i = threadIdx.x;
    if (i < 64) {
        int k = i >> 2, h = i & 3;
        float s = 0.f;
        for (int d = 0; d < 16; d++) s += We1[k * 64 + h * 16 + d] * ae1[h * 16 + d];
        g_wae1[k * 4 + h] = s;
        float s2 = 0.f;
        for (int d = 0; d < 64; d++) s2 += We2[k * 256 + h * 64 + d] * ae2[h * 64 + d];
        g_wae2[k * 4 + h] = s2;
    }
    if (i < 88) {
        int t = i >> 2, h = i & 3;
        float s = 0.f;
        for (int d = 0; d < 16; d++) s += et1[t * 64 + h * 16 + d] * ae1[h * 16 + d];
        g_tae1[t * 4 + h] = s;
        float s2 = 0.f;
        for (int d = 0; d < 64; d++) s2 += et2[t * 256 + h * 64 + d] * ae2[h * 64 + d];
        g_tae2[t * 4 + h] = s2;
    }
}

// ---------------- node projection: h = (x + nt[type]) @ Wx ; also ss/sd dots ----------------
// LAYER 1: IN=16, DIM=64, D=16, input = x param.  LAYER 2: IN=64, DIM=256, D=64, input = g_z1.
template <int LAYER, int IN, int DIM>
__global__ void k_node_proj(const float* __restrict__ x, const int* __restrict__ ntype,
                            const float* __restrict__ nt, const float* __restrict__ Wx,
                            const float* __restrict__ a_s, const float* __restrict__ a_d) {
    extern __shared__ float sm[];
    float* sWx = sm;                    // IN*DIM
    float* sNt = sWx + IN * DIM;        // 8*IN
    float* sAs = sNt + 8 * IN;          // DIM
    float* sAd = sAs + DIM;             // DIM
    float* sStage = sAd + DIM;          // (blockDim/32)*IN

    int tid = threadIdx.x;
    for (int i = tid; i < IN * DIM; i += blockDim.x) sWx[i] = Wx[i];
    for (int i = tid; i < 8 * IN; i += blockDim.x) sNt[i] = nt[i];
    for (int i = tid; i < DIM; i += blockDim.x) { sAs[i] = a_s[i]; sAd[i] = a_d[i]; }
    __syncthreads();

    int warp = tid >> 5, lane = tid & 31;
    int n = blockIdx.x * (blockDim.x >> 5) + warp;
    if (n >= NN) return;

    const float* xin = (LAYER == 1) ? x : g_z1;
    float* st = sStage + warp * IN;
    int t = ntype[n];
    for (int k = lane; k < IN; k += 32) st[k] = xin[(size_t)n * IN + k] + sNt[t * IN + k];
    __syncwarp();

    constexpr int R = DIM / 32;
    float acc[R];
#pragma unroll
    for (int j = 0; j < R; j++) acc[j] = 0.f;
#pragma unroll
    for (int k = 0; k < IN; k++) {
        float xk = st[k];
#pragma unroll
        for (int j = 0; j < R; j++) acc[j] = fmaf(xk, sWx[k * DIM + lane + 32 * j], acc[j]);
    }
#pragma unroll
    for (int j = 0; j < R; j++) g_h[(size_t)n * DIM + lane + 32 * j] = acc[j];

    if (DIM == 64) {
        // D=16: cols lane (heads 0/1 by lane half), lane+32 (heads 2/3)
        float pa = acc[0] * sAs[lane], pb = acc[1] * sAs[lane + 32];
        float qa = acc[0] * sAd[lane], qb = acc[1] * sAd[lane + 32];
#pragma unroll
        for (int o = 8; o >= 1; o >>= 1) {
            pa += __shfl_xor_sync(0xffffffffu, pa, o);
            pb += __shfl_xor_sync(0xffffffffu, pb, o);
            qa += __shfl_xor_sync(0xffffffffu, qa, o);
            qb += __shfl_xor_sync(0xffffffffu, qb, o);
        }
        if (lane == 0)  { g_ss[n * 4 + 0] = pa; g_ss[n * 4 + 2] = pb; g_sd[n * 4 + 0] = qa; g_sd[n * 4 + 2] = qb; }
        if (lane == 16) { g_ss[n * 4 + 1] = pa; g_ss[n * 4 + 3] = pb; g_sd[n * 4 + 1] = qa; g_sd[n * 4 + 3] = qb; }
    } else {
        // DIM=256, D=64: head h owns acc[2h], acc[2h+1]
        float ps[4], pd[4];
#pragma unroll
        for (int h = 0; h < 4; h++) {
            ps[h] = fmaf(acc[2 * h], sAs[lane + 64 * h], acc[2 * h + 1] * sAs[lane + 32 + 64 * h]);
            pd[h] = fmaf(acc[2 * h], sAd[lane + 64 * h], acc[2 * h + 1] * sAd[lane + 32 + 64 * h]);
#pragma unroll
            for (int o = 16; o >= 1; o >>= 1) {
                ps[h] += __shfl_xor_sync(0xffffffffu, ps[h], o);
                pd[h] += __shfl_xor_sync(0xffffffffu, pd[h], o);
            }
        }
        if (lane == 0) {
#pragma unroll
            for (int h = 0; h < 4; h++) { g_ss[n * 4 + h] = ps[h]; g_sd[n * 4 + h] = pd[h]; }
        }
    }
}

// ---------------- edge scores: sc = leaky(ss[src] + sd[dst] + ea@wae + tae[type]) ----------------
template <int LAYER>
__global__ void k_score(const int* __restrict__ ei, const float* __restrict__ eattr,
                        const int* __restrict__ etype) {
    __shared__ float sW[64];
    __shared__ float sT[88];
    const float* wae = (LAYER == 1) ? g_wae1 : g_wae2;
    const float* tae = (LAYER == 1) ? g_tae1 : g_tae2;
    if (threadIdx.x < 64) sW[threadIdx.x] = wae[threadIdx.x];
    if (threadIdx.x < 88) sT[threadIdx.x] = tae[threadIdx.x];
    __syncthreads();

    int e = blockIdx.x * blockDim.x + threadIdx.x;
    if (e >= EE) return;
    int s = ei[e], d = ei[EE + e], t = etype[e];
    float sc[4];
#pragma unroll
    for (int h = 0; h < 4; h++)
        sc[h] = g_ss[s * 4 + h] + g_sd[d * 4 + h] + sT[t * 4 + h];

    const float4* ea = (const float4*)(eattr + (size_t)e * 16);
#pragma unroll
    for (int q = 0; q < 4; q++) {
        float4 a = __ldg(ea + q);
#pragma unroll
        for (int h = 0; h < 4; h++) {
            sc[h] = fmaf(a.x, sW[(4 * q + 0) * 4 + h],
                    fmaf(a.y, sW[(4 * q + 1) * 4 + h],
                    fmaf(a.z, sW[(4 * q + 2) * 4 + h],
                    fmaf(a.w, sW[(4 * q + 3) * 4 + h], sc[h]))));
        }
    }
#pragma unroll
    for (int h = 0; h < 4; h++) sc[h] = (sc[h] > 0.f) ? sc[h] : 0.2f * sc[h];
    float4 o = make_float4(sc[0], sc[1], sc[2], sc[3]);
    *(float4*)&g_sc[(size_t)e * 4] = o;
}

// ---------------- copy z1 into output z region (residual init for layer2 mean) ----------------
__global__ void k_copy(float* __restrict__ zout) {
    int i = blockIdx.x * blockDim.x + threadIdx.x;
    if (i < NN * 64) zout[i] = g_z1[i];
}

// ---------------- aggregation: warp per dst node, 64-column block per blockIdx.y ----------------
// LAYER 1 (DIM=64): single y-block, writes g_z1 = relu(agg + x@res).
// LAYER 2 (DIM=256): 4 y-blocks (one head each), atomicAdd 0.25*acc into zout (pre-init to z1).
template <int DIM, int LAYER>
__global__ void k_aggregate(const int* __restrict__ ei, const float* __restrict__ eattr,
                            const int* __restrict__ etype,
                            const float* __restrict__ We, const float* __restrict__ et,
                            const float* __restrict__ x, const float* __restrict__ res,
                            float* __restrict__ out) {
    __shared__ float sEt[22 * 64];
    __shared__ float sRes[(LAYER == 1) ? 16 * 64 : 1];
    const int base = blockIdx.y * 64;
    int tid = threadIdx.x, lane = tid & 31;

    for (int i = tid; i < 22 * 64; i += blockDim.x) {
        int t = i >> 6, c = i & 63;
        sEt[i] = et[t * DIM + base + c];
    }
    if (LAYER == 1)
        for (int i = tid; i < 16 * 64; i += blockDim.x) sRes[i] = res[i];

    // lane-private We slice, reused across all edges
    float Wr0[16], Wr1[16];
#pragma unroll
    for (int k = 0; k < 16; k++) {
        Wr0[k] = __ldg(&We[k * DIM + base + lane]);
        Wr1[k] = __ldg(&We[k * DIM + base + lane + 32]);
    }
    __syncthreads();

    int warp = tid >> 5;
    int n = blockIdx.x * (blockDim.x >> 5) + warp;
    if (n >= NN) return;

    int r0 = g_rowptr[n], r1 = g_rowptr[n + 1];
    float acc0 = 0.f, acc1 = 0.f;

    if (r1 > r0) {
        // phase A: per-head max + denom over incoming edges
        float m0 = -3e38f, m1 = -3e38f, m2 = -3e38f, m3 = -3e38f;
        for (int i = r0 + lane; i < r1; i += 32) {
            int e = g_eidx[i];
            float4 s4 = *(const float4*)&g_sc[(size_t)e * 4];
            m0 = fmaxf(m0, s4.x); m1 = fmaxf(m1, s4.y);
            m2 = fmaxf(m2, s4.z); m3 = fmaxf(m3, s4.w);
        }
#pragma unroll
        for (int o = 16; o >= 1; o >>= 1) {
            m0 = fmaxf(m0, __shfl_xor_sync(0xffffffffu, m0, o));
            m1 = fmaxf(m1, __shfl_xor_sync(0xffffffffu, m1, o));
            m2 = fmaxf(m2, __shfl_xor_sync(0xffffffffu, m2, o));
            m3 = fmaxf(m3, __shfl_xor_sync(0xffffffffu, m3, o));
        }
        float d0 = 0.f, d1 = 0.f, d2 = 0.f, d3 = 0.f;
        for (int i = r0 + lane; i < r1; i += 32) {
            int e = g_eidx[i];
            float4 s4 = *(const float4*)&g_sc[(size_t)e * 4];
            d0 += __expf(s4.x - m0); d1 += __expf(s4.y - m1);
            d2 += __expf(s4.z - m2); d3 += __expf(s4.w - m3);
        }
#pragma unroll
        for (int o = 16; o >= 1; o >>= 1) {
            d0 += __shfl_xor_sync(0xffffffffu, d0, o);
            d1 += __shfl_xor_sync(0xffffffffu, d1, o);
            d2 += __shfl_xor_sync(0xffffffffu, d2, o);
            d3 += __shfl_xor_sync(0xffffffffu, d3, o);
        }
        float i0 = 1.f / (d0 + 1e-16f), i1 = 1.f / (d1 + 1e-16f);
        float i2 = 1.f / (d2 + 1e-16f), i3 = 1.f / (d3 + 1e-16f);

        // phase B: sequential over edges, warp-wide columns
        for (int i = r0; i < r1; i++) {
            int e = __ldg(&g_eidx[i]);
            int s = __ldg(&ei[e]);
            int t = __ldg(&etype[e]);
            float4 sv = *(const float4*)&g_sc[(size_t)e * 4];
            float a0 = __expf(sv.x - m0) * i0;
            float a1 = __expf(sv.y - m1) * i1;
            float a2 = __expf(sv.z - m2) * i2;
            float a3 = __expf(sv.w - m3) * i3;

            float ea_reg = __ldg(&eattr[(size_t)e * 16 + (lane & 15)]);
            float ev0 = sEt[t * 64 + lane], ev1 = sEt[t * 64 + lane + 32];
#pragma unroll
            for (int k = 0; k < 16; k++) {
                float eak = __shfl_sync(0xffffffffu, ea_reg, k);
                ev0 = fmaf(eak, Wr0[k], ev0);
                ev1 = fmaf(eak, Wr1[k], ev1);
            }
            const float* hrow = g_h + (size_t)s * DIM + base;
            float h0 = __ldg(&hrow[lane]), h1 = __ldg(&hrow[lane + 32]);

            float aA, aB;
            if (LAYER == 1) {
                aA = (lane < 16) ? a0 : a1;   // cols 0..31  -> heads 0/1
                aB = (lane < 16) ? a2 : a3;   // cols 32..63 -> heads 2/3
            } else {
                float ab = (blockIdx.y == 0) ? a0 : ((blockIdx.y == 1) ? a1 : ((blockIdx.y == 2) ? a2 : a3));
                aA = ab; aB = ab;
            }
            acc0 = fmaf(aA, h0 + ev0, acc0);
            acc1 = fmaf(aB, h1 + ev1, acc1);
        }
    }

    if (LAYER == 1) {
        const float4* xp = (const float4*)(x + (size_t)n * 16);
        float4 xa = __ldg(xp), xb = __ldg(xp + 1), xc = __ldg(xp + 2), xd = __ldg(xp + 3);
        float xv[16] = {xa.x, xa.y, xa.z, xa.w, xb.x, xb.y, xb.z, xb.w,
                        xc.x, xc.y, xc.z, xc.w, xd.x, xd.y, xd.z, xd.w};
        float o0 = acc0, o1 = acc1;
#pragma unroll
        for (int k = 0; k < 16; k++) {
            o0 = fmaf(xv[k], sRes[k * 64 + lane], o0);
            o1 = fmaf(xv[k], sRes[k * 64 + lane + 32], o1);
        }
        g_z1[(size_t)n * 64 + lane] = fmaxf(o0, 0.f);
        g_z1[(size_t)n * 64 + lane + 32] = fmaxf(o1, 0.f);
    } else {
        atomicAdd(&out[(size_t)n * 64 + lane], 0.25f * acc0);
        atomicAdd(&out[(size_t)n * 64 + lane + 32], 0.25f * acc1);
    }
}

// ---------------- edge decoder: warp per labeled edge ----------------
__global__ void k_decoder(const int* __restrict__ eli, const float* __restrict__ z,
                          const float* __restrict__ W1, const float* __restrict__ b1,
                          const float* __restrict__ W2, const float* __restrict__ b2,
                          float* __restrict__ pred) {
    __shared__ float sW1[128 * 64];
    __shared__ float sW2[64];
    __shared__ float sB1[64];
    __shared__ float sZZ[8 * 128];
    int tid = threadIdx.x;
    for (int i = tid; i < 128 * 64; i += blockDim.x) sW1[i] = W1[i];
    if (tid < 64) { sW2[tid] = W2[tid]; sB1[tid] = b1[tid]; }
    __syncthreads();

    int warp = tid >> 5, lane = tid & 31;
    int idx = blockIdx.x * (blockDim.x >> 5) + warp;
    if (idx >= ELN) return;
    int row = __ldg(&eli[idx]);
    int col = __ldg(&eli[ELN + idx]);
    float* zz = sZZ + warp * 128;
    zz[lane]      = __ldg(&z[(size_t)row * 64 + lane]);
    zz[lane + 32] = __ldg(&z[(size_t)row * 64 + lane + 32]);
    zz[lane + 64] = __ldg(&z[(size_t)col * 64 + lane]);
    zz[lane + 96] = __ldg(&z[(size_t)col * 64 + lane + 32]);
    __syncwarp();

    float h0 = sB1[lane], h1 = sB1[lane + 32];
#pragma unroll
    for (int k = 0; k < 128; k++) {
        float v = zz[k];
        h0 = fmaf(v, sW1[k * 64 + lane], h0);
        h1 = fmaf(v, sW1[k * 64 + lane + 32], h1);
    }
    h0 = fmaxf(h0, 0.f); h1 = fmaxf(h1, 0.f);
    float p = fmaf(h0, sW2[lane], h1 * sW2[lane + 32]);
#pragma unroll
    for (int o = 16; o >= 1; o >>= 1) p += __shfl_xor_sync(0xffffffffu, p, o);
    if (lane == 0) pred[idx] = p + __ldg(&b2[0]);
}

// ---------------- launch ----------------
extern "C" void kernel_launch(void* const* d_in, const int* in_sizes, int n_in,
                              void* d_out, int out_size) {
    const float* x     = (const float*)d_in[0];
    const int*   ei    = (const int*)d_in[1];
    const int*   ntype = (const int*)d_in[2];
    const float* eattr = (const float*)d_in[3];
    const int*   etype = (const int*)d_in[4];
    const int*   eli   = (const int*)d_in[5];
    const float* Wx1   = (const float*)d_in[6];
    const float* We1   = (const float*)d_in[7];
    const float* nt1   = (const float*)d_in[8];
    const float* et1   = (const float*)d_in[9];
    const float* as1   = (const float*)d_in[10];
    const float* ad1   = (const float*)d_in[11];
    const float* ae1   = (const float*)d_in[12];
    const float* res1  = (const float*)d_in[13];
    const float* Wx2   = (const float*)d_in[14];
    const float* We2   = (const float*)d_in[15];
    const float* nt2   = (const float*)d_in[16];
    const float* et2   = (const float*)d_in[17];
    const float* as2   = (const float*)d_in[18];
    const float* ad2   = (const float*)d_in[19];
    const float* ae2   = (const float*)d_in[20];
    const float* W1    = (const float*)d_in[21];
    const float* b1    = (const float*)d_in[22];
    const float* W2    = (const float*)d_in[23];
    const float* b2    = (const float*)d_in[24];

    float* pred = (float*)d_out;
    float* zout = pred + ELN;

    // CSR build (dst -> incoming edge list)
    k_zero_cnt<<<(NN + 255) / 256, 256>>>();
    k_count<<<(EE + 255) / 256, 256>>>(ei);
    k_scan<<<1, 1024>>>();
    k_initcur<<<(NN + 255) / 256, 256>>>();
    k_fill<<<(EE + 255) / 256, 256>>>(ei);
    k_prec<<<1, 128>>>(We1, ae1, et1, We2, ae2, et2);

    // ---- layer 1 ----
    size_t sm1 = (size_t)(16 * 64 + 8 * 16 + 64 + 64 + 8 * 16) * sizeof(float);
    k_node_proj<1, 16, 64><<<(NN + 7) / 8, 256, sm1>>>(x, ntype, nt1, Wx1, as1, ad1);
    k_score<1><<<(EE + 255) / 256, 256>>>(ei, eattr, etype);
    k_aggregate<64, 1><<<dim3((NN + 7) / 8, 1), 256>>>(ei, eattr, etype, We1, et1, x, res1, nullptr);

    // ---- layer 2 ----
    size_t sm2 = (size_t)(64 * 256 + 8 * 64 + 256 + 256 + 8 * 64) * sizeof(float);
    cudaFuncSetAttribute((const void*)k_node_proj<2, 64, 256>,
                         cudaFuncAttributeMaxDynamicSharedMemorySize, (int)sm2);
    k_node_proj<2, 64, 256><<<(NN + 7) / 8, 256, sm2>>>(x, ntype, nt2, Wx2, as2, ad2);
    k_score<2><<<(EE + 255) / 256, 256>>>(ei, eattr, etype);
    k_copy<<<(NN * 64 + 255) / 256, 256>>>(zout);
    k_aggregate<256, 2><<<dim3((NN + 7) / 8, 4), 256>>>(ei, eattr, etype, We2, et2, nullptr, nullptr, zout);

    // ---- decoder ----
    k_decoder<<<(ELN + 7) / 8, 256>>>(eli, zout, W1, b1, W2, b2, pred);
}

// round 2
// speedup vs baseline: 2.4442x; 2.4442x over previous
#include <cuda_runtime.h>
#include <cstdint>

#define NN 100000
#define EE 600000
#define ELN 200000

// ---------------- device scratch ----------------
__device__ float g_h[(size_t)NN * 256];   // node projections (layer1: stride 64, layer2: stride 256)
__device__ float g_z1[(size_t)NN * 64];   // layer1 output (post-residual, post-relu)
__device__ float g_sc[(size_t)EE * 4];    // per-edge per-head scores, later alpha (in place)
__device__ float g_ss[NN * 4];            // h . a_s per node per head
__device__ float g_sd[NN * 4];            // h . a_d per node per head
__device__ int   g_cnt[NN];
__device__ int   g_rowptr[NN + 1];
__device__ int   g_cur[NN];
__device__ int   g_eidx[EE];
__device__ float g_wae1[64], g_tae1[88];
__device__ float g_wae2[64], g_tae2[88];

// ---------------- CSR build ----------------
__global__ void k_zero_cnt() {
    int i = blockIdx.x * blockDim.x + threadIdx.x;
    if (i < NN) g_cnt[i] = 0;
}

__global__ void k_count(const int* __restrict__ ei) {
    int e = blockIdx.x * blockDim.x + threadIdx.x;
    if (e < EE) atomicAdd(&g_cnt[ei[EE + e]], 1);
}

// scan + cur-init + (We.a_e)/(et.a_e) precompute tables, one launch
__global__ void k_scanfuse(const float* __restrict__ We1, const float* __restrict__ ae1,
                           const float* __restrict__ et1,
                           const float* __restrict__ We2, const float* __restrict__ ae2,
                           const float* __restrict__ et2) {
    __shared__ int sp[1024];
    int tid = threadIdx.x;

    // small precompute first (independent of scan)
    if (tid < 64) {
        int k = tid >> 2, h = tid & 3;
        float s = 0.f;
        for (int d = 0; d < 16; d++) s += We1[k * 64 + h * 16 + d] * ae1[h * 16 + d];
        g_wae1[k * 4 + h] = s;
        float s2 = 0.f;
        for (int d = 0; d < 64; d++) s2 += We2[k * 256 + h * 64 + d] * ae2[h * 64 + d];
        g_wae2[k * 4 + h] = s2;
    }
    if (tid < 88) {
        int t = tid >> 2, h = tid & 3;
        float s = 0.f;
        for (int d = 0; d < 16; d++) s += et1[t * 64 + h * 16 + d] * ae1[h * 16 + d];
        g_tae1[t * 4 + h] = s;
        float s2 = 0.f;
        for (int d = 0; d < 64; d++) s2 += et2[t * 256 + h * 64 + d] * ae2[h * 64 + d];
        g_tae2[t * 4 + h] = s2;
    }

    const int chunk = (NN + 1023) >> 10;
    int st = tid * chunk;
    int en = st + chunk; if (en > NN) en = NN;
    int s = 0;
    for (int i = st; i < en; i++) s += g_cnt[i];
    sp[tid] = s;
    __syncthreads();
    for (int o = 1; o < 1024; o <<= 1) {
        int v = (tid >= o) ? sp[tid - o] : 0;
        __syncthreads();
        sp[tid] += v;
        __syncthreads();
    }
    int b = sp[tid] - s;
    for (int i = st; i < en; i++) { g_rowptr[i] = b; g_cur[i] = b; b += g_cnt[i]; }
    if (tid == 1023) g_rowptr[NN] = sp[1023];
}

__global__ void k_fill(const int* __restrict__ ei) {
    int e = blockIdx.x * blockDim.x + threadIdx.x;
    if (e < EE) {
        int d = ei[EE + e];
        int p = atomicAdd(&g_cur[d], 1);
        g_eidx[p] = e;
    }
}

// ---------------- layer1 node projection (warp-per-node) + ss/sd dots ----------------
__global__ void k_proj1(const float* __restrict__ x, const int* __restrict__ ntype,
                        const float* __restrict__ nt, const float* __restrict__ Wx,
                        const float* __restrict__ a_s, const float* __restrict__ a_d) {
    __shared__ float sWx[16 * 64];
    __shared__ float sNt[8 * 16];
    __shared__ float sAs[64];
    __shared__ float sAd[64];
    __shared__ float sStage[8 * 16];

    int tid = threadIdx.x;
    for (int i = tid; i < 16 * 64; i += 256) sWx[i] = Wx[i];
    for (int i = tid; i < 8 * 16; i += 256) sNt[i] = nt[i];
    if (tid < 64) { sAs[tid] = a_s[tid]; sAd[tid] = a_d[tid]; }
    __syncthreads();

    int warp = tid >> 5, lane = tid & 31;
    int n = blockIdx.x * 8 + warp;
    if (n >= NN) return;

    float* st = sStage + warp * 16;
    int t = ntype[n];
    if (lane < 16) st[lane] = x[(size_t)n * 16 + lane] + sNt[t * 16 + lane];
    __syncwarp();

    float acc0 = 0.f, acc1 = 0.f;
#pragma unroll
    for (int k = 0; k < 16; k++) {
        float xk = st[k];
        acc0 = fmaf(xk, sWx[k * 64 + lane], acc0);
        acc1 = fmaf(xk, sWx[k * 64 + lane + 32], acc1);
    }
    g_h[(size_t)n * 64 + lane] = acc0;
    g_h[(size_t)n * 64 + lane + 32] = acc1;

    float pa = acc0 * sAs[lane], pb = acc1 * sAs[lane + 32];
    float qa = acc0 * sAd[lane], qb = acc1 * sAd[lane + 32];
#pragma unroll
    for (int o = 8; o >= 1; o >>= 1) {
        pa += __shfl_xor_sync(0xffffffffu, pa, o);
        pb += __shfl_xor_sync(0xffffffffu, pb, o);
        qa += __shfl_xor_sync(0xffffffffu, qa, o);
        qb += __shfl_xor_sync(0xffffffffu, qb, o);
    }
    if (lane == 0)  { g_ss[n * 4 + 0] = pa; g_ss[n * 4 + 2] = pb; g_sd[n * 4 + 0] = qa; g_sd[n * 4 + 2] = qb; }
    if (lane == 16) { g_ss[n * 4 + 1] = pa; g_ss[n * 4 + 3] = pb; g_sd[n * 4 + 1] = qa; g_sd[n * 4 + 3] = qb; }
}

// ---------------- edge scores (raw, post-leaky) ----------------
template <int LAYER>
__global__ void k_score(const int* __restrict__ ei, const float* __restrict__ eattr,
                        const int* __restrict__ etype) {
    __shared__ float sW[64];
    __shared__ float sT[88];
    const float* wae = (LAYER == 1) ? g_wae1 : g_wae2;
    const float* tae = (LAYER == 1) ? g_tae1 : g_tae2;
    if (threadIdx.x < 64) sW[threadIdx.x] = wae[threadIdx.x];
    if (threadIdx.x < 88) sT[threadIdx.x] = tae[threadIdx.x];
    __syncthreads();

    int e = blockIdx.x * blockDim.x + threadIdx.x;
    if (e >= EE) return;
    int s = ei[e], d = ei[EE + e], t = etype[e];
    float sc[4];
#pragma unroll
    for (int h = 0; h < 4; h++)
        sc[h] = g_ss[s * 4 + h] + g_sd[d * 4 + h] + sT[t * 4 + h];

    const float4* ea = (const float4*)(eattr + (size_t)e * 16);
#pragma unroll
    for (int q = 0; q < 4; q++) {
        float4 a = __ldg(ea + q);
#pragma unroll
        for (int h = 0; h < 4; h++) {
            sc[h] = fmaf(a.x, sW[(4 * q + 0) * 4 + h],
                    fmaf(a.y, sW[(4 * q + 1) * 4 + h],
                    fmaf(a.z, sW[(4 * q + 2) * 4 + h],
                    fmaf(a.w, sW[(4 * q + 3) * 4 + h], sc[h]))));
        }
    }
#pragma unroll
    for (int h = 0; h < 4; h++) sc[h] = (sc[h] > 0.f) ? sc[h] : 0.2f * sc[h];
    float4 o = make_float4(sc[0], sc[1], sc[2], sc[3]);
    *(float4*)&g_sc[(size_t)e * 4] = o;
}

// ---------------- alpha: thread-per-node online softmax, alpha written over g_sc ----------------
__global__ void k_alpha() {
    int n = blockIdx.x * blockDim.x + threadIdx.x;
    if (n >= NN) return;
    int r0 = g_rowptr[n], r1 = g_rowptr[n + 1];
    if (r1 <= r0) return;
    float m0 = -3e38f, m1 = -3e38f, m2 = -3e38f, m3 = -3e38f;
    float d0 = 0.f, d1 = 0.f, d2 = 0.f, d3 = 0.f;
    for (int i = r0; i < r1; i++) {
        int e = __ldg(&g_eidx[i]);
        float4 s = *(const float4*)&g_sc[(size_t)e * 4];
        if (s.x > m0) { d0 *= __expf(m0 - s.x); m0 = s.x; }
        d0 += __expf(s.x - m0);
        if (s.y > m1) { d1 *= __expf(m1 - s.y); m1 = s.y; }
        d1 += __expf(s.y - m1);
        if (s.z > m2) { d2 *= __expf(m2 - s.z); m2 = s.z; }
        d2 += __expf(s.z - m2);
        if (s.w > m3) { d3 *= __expf(m3 - s.w); m3 = s.w; }
        d3 += __expf(s.w - m3);
    }
    float i0 = 1.f / (d0 + 1e-16f), i1 = 1.f / (d1 + 1e-16f);
    float i2 = 1.f / (d2 + 1e-16f), i3 = 1.f / (d3 + 1e-16f);
    for (int i = r0; i < r1; i++) {
        int e = __ldg(&g_eidx[i]);
        float4 s = *(const float4*)&g_sc[(size_t)e * 4];
        float4 a = make_float4(__expf(s.x - m0) * i0, __expf(s.y - m1) * i1,
                               __expf(s.z - m2) * i2, __expf(s.w - m3) * i3);
        *(float4*)&g_sc[(size_t)e * 4] = a;
    }
}

// ---------------- layer1 aggregation: warp-per-node, single pass ----------------
__global__ void __launch_bounds__(256) k_agg1(const int* __restrict__ ei, const float* __restrict__ eattr,
                                              const int* __restrict__ etype,
                                              const float* __restrict__ We, const float* __restrict__ et,
                                              const float* __restrict__ x, const float* __restrict__ res) {
    __shared__ float sEt[22 * 64];
    __shared__ float sWe[16 * 64];
    __shared__ float sRes[16 * 64];
    __shared__ float sWs[8 * 64];
    int tid = threadIdx.x, L = tid & 31, w = tid >> 5;
    for (int i = tid; i < 22 * 64; i += 256) sEt[i] = et[i];
    for (int i = tid; i < 16 * 64; i += 256) { sWe[i] = We[i]; sRes[i] = res[i]; }
    __syncthreads();

    int n = blockIdx.x * 8 + w;
    if (n >= NN) return;
    int r0 = g_rowptr[n], r1 = g_rowptr[n + 1];

    float2 acc = make_float2(0.f, 0.f);
    float w0 = 0.f, w1 = 0.f;
    const int H = L >> 3;        // head of cols 2L, 2L+1
    const int hb = L >> 4;       // wsum head base

    for (int base = r0; base < r1; base += 32) {
        int nv = min(32, r1 - base);
        int e = 0, s = 0, t = 0;
        float4 al = make_float4(0.f, 0.f, 0.f, 0.f);
        if (L < nv) {
            e = __ldg(&g_eidx[base + L]);
            s = __ldg(&ei[e]);
            t = __ldg(&etype[e]);
            al = *(const float4*)&g_sc[(size_t)e * 4];
        }
        for (int j = 0; j < nv; j++) {
            int ej = __shfl_sync(0xffffffffu, e, j);
            int sj = __shfl_sync(0xffffffffu, s, j);
            int tj = __shfl_sync(0xffffffffu, t, j);
            float a0 = __shfl_sync(0xffffffffu, al.x, j);
            float a1 = __shfl_sync(0xffffffffu, al.y, j);
            float a2 = __shfl_sync(0xffffffffu, al.z, j);
            float a3 = __shfl_sync(0xffffffffu, al.w, j);
            float ea = __ldg(&eattr[(size_t)ej * 16 + (L & 15)]);
            float2 h2 = *(const float2*)&g_h[(size_t)sj * 64 + 2 * L];
            float2 ev = *(const float2*)&sEt[tj * 64 + 2 * L];
            float ah = (H == 0) ? a0 : ((H == 1) ? a1 : ((H == 2) ? a2 : a3));
            acc.x = fmaf(ah, h2.x + ev.x, acc.x);
            acc.y = fmaf(ah, h2.y + ev.y, acc.y);
            float aw0 = hb ? a1 : a0, aw1 = hb ? a3 : a2;
            w0 = fmaf(aw0, ea, w0);
            w1 = fmaf(aw1, ea, w1);
        }
    }
    // stage wsum: sWs[w*64 + h*16 + k]; w0 -> h=hb (idx L), w1 -> h=2+hb (idx 32+L)
    sWs[w * 64 + L] = w0;
    sWs[w * 64 + 32 + L] = w1;
    __syncwarp();

#pragma unroll
    for (int k = 0; k < 16; k++) {
        float wk = sWs[w * 64 + H * 16 + k];
        float2 we = *(const float2*)&sWe[k * 64 + 2 * L];
        acc.x = fmaf(wk, we.x, acc.x);
        acc.y = fmaf(wk, we.y, acc.y);
    }
    // residual x @ res
    const float4* xp = (const float4*)(x + (size_t)n * 16);
    float4 xa = __ldg(xp), xb = __ldg(xp + 1), xc = __ldg(xp + 2), xd = __ldg(xp + 3);
    float xv[16] = {xa.x, xa.y, xa.z, xa.w, xb.x, xb.y, xb.z, xb.w,
                    xc.x, xc.y, xc.z, xc.w, xd.x, xd.y, xd.z, xd.w};
#pragma unroll
    for (int k = 0; k < 16; k++) {
        float2 rv = *(const float2*)&sRes[k * 64 + 2 * L];
        acc.x = fmaf(xv[k], rv.x, acc.x);
        acc.y = fmaf(xv[k], rv.y, acc.y);
    }
    g_z1[(size_t)n * 64 + 2 * L]     = fmaxf(acc.x, 0.f);
    g_z1[(size_t)n * 64 + 2 * L + 1] = fmaxf(acc.y, 0.f);
}

// ---------------- layer2 projection: tiled GEMM (z1 + nt2[type]) @ Wx2 + fused ss/sd ----------------
__global__ void __launch_bounds__(256) k_proj2(const int* __restrict__ ntype, const float* __restrict__ nt,
                                               const float* __restrict__ Wx,
                                               const float* __restrict__ a_s, const float* __restrict__ a_d) {
    extern __shared__ float sm[];
    float* sA = sm;              // 128*68
    float* sB = sA + 128 * 68;   // 64*64
    float* sNt = sB + 4096;      // 8*64
    float* sAs = sNt + 512;      // 64
    float* sAd = sAs + 64;       // 64
    int*   sTy = (int*)(sAd + 64); // 128

    int tid = threadIdx.x;
    int by = blockIdx.y;
    int rbase = blockIdx.x * 128;

    for (int i = tid; i < 512; i += 256) sNt[i] = nt[i];
    if (tid < 64) { sAs[tid] = a_s[by * 64 + tid]; sAd[tid] = a_d[by * 64 + tid]; }
    if (tid < 128) { int r = rbase + tid; sTy[tid] = (r < NN) ? ntype[r] : 0; }
    __syncthreads();

    for (int i = tid; i < 1024; i += 256) {
        int k = i >> 4, cg = i & 15;
        float4 v = *(const float4*)&Wx[(size_t)k * 256 + by * 64 + cg * 4];
        *(float4*)&sB[k * 64 + cg * 4] = v;
    }
    for (int i = tid; i < 2048; i += 256) {
        int r = i >> 4, sg = i & 15;
        int gr = rbase + r;
        float4 v = make_float4(0.f, 0.f, 0.f, 0.f);
        if (gr < NN) {
            v = *(const float4*)&g_z1[(size_t)gr * 64 + sg * 4];
            float4 nv = *(const float4*)&sNt[sTy[r] * 64 + sg * 4];
            v.x += nv.x; v.y += nv.y; v.z += nv.z; v.w += nv.w;
        }
        *(float4*)&sA[r * 68 + sg * 4] = v;
    }
    __syncthreads();

    int tx = tid & 15, ty = tid >> 4;
    int c0 = tx * 4, r0 = ty * 8;
    float4 acc[8];
#pragma unroll
    for (int i = 0; i < 8; i++) acc[i] = make_float4(0.f, 0.f, 0.f, 0.f);

#pragma unroll 4
    for (int k = 0; k < 64; k++) {
        float4 b = *(const float4*)&sB[k * 64 + c0];
#pragma unroll
        for (int i = 0; i < 8; i++) {
            float a = sA[(r0 + i) * 68 + k];
            acc[i].x = fmaf(a, b.x, acc[i].x);
            acc[i].y = fmaf(a, b.y, acc[i].y);
            acc[i].z = fmaf(a, b.z, acc[i].z);
            acc[i].w = fmaf(a, b.w, acc[i].w);
        }
    }

    float ps[8], pd[8];
#pragma unroll
    for (int i = 0; i < 8; i++) {
        int gr = rbase + r0 + i;
        if (gr < NN) *(float4*)&g_h[(size_t)gr * 256 + by * 64 + c0] = acc[i];
        ps[i] = acc[i].x * sAs[c0] + acc[i].y * sAs[c0 + 1] + acc[i].z * sAs[c0 + 2] + acc[i].w * sAs[c0 + 3];
        pd[i] = acc[i].x * sAd[c0] + acc[i].y * sAd[c0 + 1] + acc[i].z * sAd[c0 + 2] + acc[i].w * sAd[c0 + 3];
    }
#pragma unroll
    for (int o = 1; o < 16; o <<= 1) {
#pragma unroll
        for (int i = 0; i < 8; i++) {
            ps[i] += __shfl_xor_sync(0xffffffffu, ps[i], o);
            pd[i] += __shfl_xor_sync(0xffffffffu, pd[i], o);
        }
    }
    if (tx == 0) {
#pragma unroll
        for (int i = 0; i < 8; i++) {
            int gr = rbase + r0 + i;
            if (gr < NN) { g_ss[gr * 4 + by] = ps[i]; g_sd[gr * 4 + by] = pd[i]; }
        }
    }
}

// ---------------- layer2 aggregation: warp-per-node, all 256 cols, single pass ----------------
__global__ void __launch_bounds__(256) k_agg2(const int* __restrict__ ei, const float* __restrict__ eattr,
                                              const int* __restrict__ etype,
                                              const float* __restrict__ We, const float* __restrict__ et,
                                              float* __restrict__ zout) {
    __shared__ float4 sEt[22 * 64];
    __shared__ float4 sWe[16 * 64];
    __shared__ float  sWs[8 * 64];
    int tid = threadIdx.x, L = tid & 31, w = tid >> 5;
    for (int i = tid; i < 22 * 64; i += 256) sEt[i] = *(const float4*)&et[(size_t)i * 4];
    for (int i = tid; i < 16 * 64; i += 256) sWe[i] = *(const float4*)&We[(size_t)i * 4];
    __syncthreads();

    int n = blockIdx.x * 8 + w;
    if (n >= NN) return;
    int r0 = g_rowptr[n], r1 = g_rowptr[n + 1];

    float4 acc0 = make_float4(0.f, 0.f, 0.f, 0.f);
    float4 acc1 = make_float4(0.f, 0.f, 0.f, 0.f);
    float w0 = 0.f, w1 = 0.f;
    const int hb = L >> 4;  // head of acc0 cols (4L..4L+3); acc1 head = 2+hb

    for (int base = r0; base < r1; base += 32) {
        int nv = min(32, r1 - base);
        int e = 0, s = 0, t = 0;
        float4 al = make_float4(0.f, 0.f, 0.f, 0.f);
        if (L < nv) {
            e = __ldg(&g_eidx[base + L]);
            s = __ldg(&ei[e]);
            t = __ldg(&etype[e]);
            al = *(const float4*)&g_sc[(size_t)e * 4];
        }
        for (int j = 0; j < nv; j++) {
            int ej = __shfl_sync(0xffffffffu, e, j);
            int sj = __shfl_sync(0xffffffffu, s, j);
            int tj = __shfl_sync(0xffffffffu, t, j);
            float a0 = __shfl_sync(0xffffffffu, al.x, j);
            float a1 = __shfl_sync(0xffffffffu, al.y, j);
            float a2 = __shfl_sync(0xffffffffu, al.z, j);
            float a3 = __shfl_sync(0xffffffffu, al.w, j);
            float aA = hb ? a1 : a0;
            float aB = hb ? a3 : a2;
            float ea = __ldg(&eattr[(size_t)ej * 16 + (L & 15)]);
            const float4* hp = (const float4*)(g_h + (size_t)sj * 256);
            float4 h0 = __ldg(hp + L);
            float4 h1 = __ldg(hp + 32 + L);
            float4 e0 = sEt[tj * 64 + L];
            float4 e1 = sEt[tj * 64 + 32 + L];
            acc0.x = fmaf(aA, h0.x + e0.x, acc0.x);
            acc0.y = fmaf(aA, h0.y + e0.y, acc0.y);
            acc0.z = fmaf(aA, h0.z + e0.z, acc0.z);
            acc0.w = fmaf(aA, h0.w + e0.w, acc0.w);
            acc1.x = fmaf(aB, h1.x + e1.x, acc1.x);
            acc1.y = fmaf(aB, h1.y + e1.y, acc1.y);
            acc1.z = fmaf(aB, h1.z + e1.z, acc1.z);
            acc1.w = fmaf(aB, h1.w + e1.w, acc1.w);
            w0 = fmaf(aA, ea, w0);
            w1 = fmaf(aB, ea, w1);
        }
    }
    sWs[w * 64 + L] = w0;        // (h=hb, k=L&15)
    sWs[w * 64 + 32 + L] = w1;   // (h=2+hb, k)
    __syncwarp();

    const int H0 = hb, H1 = 2 + hb;
#pragma unroll
    for (int k = 0; k < 16; k++) {
        float k0 = sWs[w * 64 + H0 * 16 + k];
        float k1 = sWs[w * 64 + H1 * 16 + k];
        float4 we0 = sWe[k * 64 + L];
        float4 we1 = sWe[k * 64 + 32 + L];
        acc0.x = fmaf(k0, we0.x, acc0.x); acc0.y = fmaf(k0, we0.y, acc0.y);
        acc0.z = fmaf(k0, we0.z, acc0.z); acc0.w = fmaf(k0, we0.w, acc0.w);
        acc1.x = fmaf(k1, we1.x, acc1.x); acc1.y = fmaf(k1, we1.y, acc1.y);
        acc1.z = fmaf(k1, we1.z, acc1.z); acc1.w = fmaf(k1, we1.w, acc1.w);
    }
    float4 sm4;
    sm4.x = acc0.x + acc1.x; sm4.y = acc0.y + acc1.y;
    sm4.z = acc0.z + acc1.z; sm4.w = acc0.w + acc1.w;
    sm4.x += __shfl_xor_sync(0xffffffffu, sm4.x, 16);
    sm4.y += __shfl_xor_sync(0xffffffffu, sm4.y, 16);
    sm4.z += __shfl_xor_sync(0xffffffffu, sm4.z, 16);
    sm4.w += __shfl_xor_sync(0xffffffffu, sm4.w, 16);
    if (L < 16) {
        float4 z1v = *(const float4*)&g_z1[(size_t)n * 64 + 4 * L];
        float4 o;
        o.x = z1v.x + 0.25f * sm4.x;
        o.y = z1v.y + 0.25f * sm4.y;
        o.z = z1v.z + 0.25f * sm4.z;
        o.w = z1v.w + 0.25f * sm4.w;
        *(float4*)&zout[(size_t)n * 64 + 4 * L] = o;
    }
}

// ---------------- decoder: tiled GEMM, 64 edges x 64 cols per block ----------------
__global__ void __launch_bounds__(256) k_dec(const int* __restrict__ eli, const float* __restrict__ z,
                                             const float* __restrict__ W1, const float* __restrict__ b1,
                                             const float* __restrict__ W2, const float* __restrict__ b2,
                                             float* __restrict__ pred) {
    extern __shared__ float sm[];
    float* sA = sm;                 // 64*132 (edge-major, padded)
    float* sB = sA + 64 * 132;      // 128*64
    int*   sR = (int*)(sB + 8192);  // 64
    int*   sC = sR + 64;            // 64
    float* sb1 = (float*)(sC + 64); // 64
    float* sw2 = sb1 + 64;          // 64

    int tid = threadIdx.x;
    int ebase = blockIdx.x * 64;
    if (tid < 64) sR[tid] = __ldg(&eli[ebase + tid]);
    else if (tid < 128) sC[tid - 64] = __ldg(&eli[ELN + ebase + tid - 64]);
    if (tid < 64) { sb1[tid] = b1[tid]; sw2[tid] = W2[tid]; }
    for (int i = tid; i < 2048; i += 256)
        *(float4*)&sB[i * 4] = *(const float4*)&W1[(size_t)i * 4];
    __syncthreads();
    for (int i = tid; i < 2048; i += 256) {
        int e = i >> 5, sg = i & 31;
        int node = (sg < 16) ? sR[e] : sC[e];
        float4 v = *(const float4*)&z[(size_t)node * 64 + (sg & 15) * 4];
        *(float4*)&sA[e * 132 + sg * 4] = v;
    }
    __syncthreads();

    int tx = tid & 15, ty = tid >> 4;
    int c0 = tx * 4, r0 = ty * 4;
    float4 acc[4];
#pragma unroll
    for (int i = 0; i < 4; i++) acc[i] = make_float4(0.f, 0.f, 0.f, 0.f);

#pragma unroll 4
    for (int k = 0; k < 128; k++) {
        float4 b = *(const float4*)&sB[k * 64 + c0];
#pragma unroll
        for (int i = 0; i < 4; i++) {
            float a = sA[(r0 + i) * 132 + k];
            acc[i].x = fmaf(a, b.x, acc[i].x);
            acc[i].y = fmaf(a, b.y, acc[i].y);
            acc[i].z = fmaf(a, b.z, acc[i].z);
            acc[i].w = fmaf(a, b.w, acc[i].w);
        }
    }

    float p[4];
#pragma unroll
    for (int i = 0; i < 4; i++) {
        float hx = fmaxf(acc[i].x + sb1[c0],     0.f);
        float hy = fmaxf(acc[i].y + sb1[c0 + 1], 0.f);
        float hz = fmaxf(acc[i].z + sb1[c0 + 2], 0.f);
        float hw = fmaxf(acc[i].w + sb1[c0 + 3], 0.f);
        p[i] = hx * sw2[c0] + hy * sw2[c0 + 1] + hz * sw2[c0 + 2] + hw * sw2[c0 + 3];
    }
#pragma unroll
    for (int o = 1; o < 16; o <<= 1) {
#pragma unroll
        for (int i = 0; i < 4; i++) p[i] += __shfl_xor_sync(0xffffffffu, p[i], o);
    }
    if (tx == 0) {
        float bb = __ldg(&b2[0]);
#pragma unroll
        for (int i = 0; i < 4; i++) pred[ebase + r0 + i] = p[i] + bb;
    }
}

// ---------------- launch ----------------
extern "C" void kernel_launch(void* const* d_in, const int* in_sizes, int n_in,
                              void* d_out, int out_size) {
    const float* x     = (const float*)d_in[0];
    const int*   ei    = (const int*)d_in[1];
    const int*   ntype = (const int*)d_in[2];
    const float* eattr = (const float*)d_in[3];
    const int*   etype = (const int*)d_in[4];
    const int*   eli   = (const int*)d_in[5];
    const float* Wx1   = (const float*)d_in[6];
    const float* We1   = (const float*)d_in[7];
    const float* nt1   = (const float*)d_in[8];
    const float* et1   = (const float*)d_in[9];
    const float* as1   = (const float*)d_in[10];
    const float* ad1   = (const float*)d_in[11];
    const float* ae1   = (const float*)d_in[12];
    const float* res1  = (const float*)d_in[13];
    const float* Wx2   = (const float*)d_in[14];
    const float* We2   = (const float*)d_in[15];
    const float* nt2   = (const float*)d_in[16];
    const float* et2   = (const float*)d_in[17];
    const float* as2   = (const float*)d_in[18];
    const float* ad2   = (const float*)d_in[19];
    const float* ae2   = (const float*)d_in[20];
    const float* W1    = (const float*)d_in[21];
    const float* b1    = (const float*)d_in[22];
    const float* W2    = (const float*)d_in[23];
    const float* b2    = (const float*)d_in[24];

    float* pred = (float*)d_out;
    float* zout = pred + ELN;

    // CSR build
    k_zero_cnt<<<(NN + 255) / 256, 256>>>();
    k_count<<<(EE + 255) / 256, 256>>>(ei);
    k_scanfuse<<<1, 1024>>>(We1, ae1, et1, We2, ae2, et2);
    k_fill<<<(EE + 255) / 256, 256>>>(ei);

    // layer 1
    k_proj1<<<(NN + 7) / 8, 256>>>(x, ntype, nt1, Wx1, as1, ad1);
    k_score<1><<<(EE + 255) / 256, 256>>>(ei, eattr, etype);
    k_alpha<<<(NN + 255) / 256, 256>>>();
    k_agg1<<<(NN + 7) / 8, 256>>>(ei, eattr, etype, We1, et1, x, res1);

    // layer 2
    size_t smP2 = (size_t)(128 * 68 + 64 * 64 + 512 + 64 + 64 + 128) * sizeof(float);
    cudaFuncSetAttribute((const void*)k_proj2, cudaFuncAttributeMaxDynamicSharedMemorySize, (int)smP2);
    k_proj2<<<dim3((NN + 127) / 128, 4), 256, smP2>>>(ntype, nt2, Wx2, as2, ad2);
    k_score<2><<<(EE + 255) / 256, 256>>>(ei, eattr, etype);
    k_alpha<<<(NN + 255) / 256, 256>>>();
    k_agg2<<<(NN + 7) / 8, 256>>>(ei, eattr, etype, We2, et2, zout);

    // decoder
    size_t smD = (size_t)(64 * 132 + 128 * 64 + 64 + 64 + 64 + 64) * sizeof(float);
    cudaFuncSetAttribute((const void*)k_dec, cudaFuncAttributeMaxDynamicSharedMemorySize, (int)smD);
    k_dec<<<ELN / 64, 256, smD>>>(eli, zout, W1, b1, W2, b2, pred);
}

// round 3
// speedup vs baseline: 2.5049x; 1.0248x over previous
#include <cuda_runtime.h>
#include <cstdint>

#define NN 100000
#define EE 600000
#define ELN 200000

// ---------------- device scratch ----------------
__device__ float g_h[(size_t)NN * 256];   // node projections (layer1: stride 64, layer2: stride 256)
__device__ float g_z1[(size_t)NN * 64];   // layer1 output
__device__ float g_sc[(size_t)EE * 4];    // per-edge per-head scores, CSR order
__device__ float g_ss[NN * 4];            // h . a_s
__device__ float g_sd[NN * 4];            // h . a_d
__device__ int   g_cnt[NN];
__device__ int   g_rowptr[NN + 1];
__device__ int   g_cur[NN];
__device__ int   g_pos[EE];               // edge -> CSR slot
__device__ int2  g_meta[EE];              // CSR slot -> (src, etype)
__device__ int   g_eorig[EE];             // CSR slot -> original edge id
__device__ float g_wae1[64], g_tae1[88];
__device__ float g_wae2[64], g_tae2[88];

// ---------------- CSR build ----------------
__global__ void k_zero_cnt() {
    int i = blockIdx.x * blockDim.x + threadIdx.x;
    if (i < NN) g_cnt[i] = 0;
}

__global__ void k_count(const int* __restrict__ ei) {
    int e = blockIdx.x * blockDim.x + threadIdx.x;
    if (e < EE) atomicAdd(&g_cnt[ei[EE + e]], 1);
}

__global__ void k_scanfuse(const float* __restrict__ We1, const float* __restrict__ ae1,
                           const float* __restrict__ et1,
                           const float* __restrict__ We2, const float* __restrict__ ae2,
                           const float* __restrict__ et2) {
    __shared__ int sp[1024];
    int tid = threadIdx.x;
    if (tid < 64) {
        int k = tid >> 2, h = tid & 3;
        float s = 0.f;
        for (int d = 0; d < 16; d++) s += We1[k * 64 + h * 16 + d] * ae1[h * 16 + d];
        g_wae1[k * 4 + h] = s;
        float s2 = 0.f;
        for (int d = 0; d < 64; d++) s2 += We2[k * 256 + h * 64 + d] * ae2[h * 64 + d];
        g_wae2[k * 4 + h] = s2;
    }
    if (tid < 88) {
        int t = tid >> 2, h = tid & 3;
        float s = 0.f;
        for (int d = 0; d < 16; d++) s += et1[t * 64 + h * 16 + d] * ae1[h * 16 + d];
        g_tae1[t * 4 + h] = s;
        float s2 = 0.f;
        for (int d = 0; d < 64; d++) s2 += et2[t * 256 + h * 64 + d] * ae2[h * 64 + d];
        g_tae2[t * 4 + h] = s2;
    }
    const int chunk = (NN + 1023) >> 10;
    int st = tid * chunk;
    int en = st + chunk; if (en > NN) en = NN;
    int s = 0;
    for (int i = st; i < en; i++) s += g_cnt[i];
    sp[tid] = s;
    __syncthreads();
    for (int o = 1; o < 1024; o <<= 1) {
        int v = (tid >= o) ? sp[tid - o] : 0;
        __syncthreads();
        sp[tid] += v;
        __syncthreads();
    }
    int b = sp[tid] - s;
    for (int i = st; i < en; i++) { g_rowptr[i] = b; g_cur[i] = b; b += g_cnt[i]; }
    if (tid == 1023) g_rowptr[NN] = sp[1023];
}

__global__ void k_fill(const int* __restrict__ ei, const int* __restrict__ etype) {
    int e = blockIdx.x * blockDim.x + threadIdx.x;
    if (e < EE) {
        int d = ei[EE + e];
        int p = atomicAdd(&g_cur[d], 1);
        g_pos[e] = p;
        g_meta[p] = make_int2(ei[e], etype[e]);
        g_eorig[p] = e;
    }
}

// ---------------- layer1 node projection + ss/sd dots ----------------
__global__ void k_proj1(const float* __restrict__ x, const int* __restrict__ ntype,
                        const float* __restrict__ nt, const float* __restrict__ Wx,
                        const float* __restrict__ a_s, const float* __restrict__ a_d) {
    __shared__ float sWx[16 * 64];
    __shared__ float sNt[8 * 16];
    __shared__ float sAs[64];
    __shared__ float sAd[64];
    __shared__ float sStage[8 * 16];

    int tid = threadIdx.x;
    for (int i = tid; i < 16 * 64; i += 256) sWx[i] = Wx[i];
    for (int i = tid; i < 8 * 16; i += 256) sNt[i] = nt[i];
    if (tid < 64) { sAs[tid] = a_s[tid]; sAd[tid] = a_d[tid]; }
    __syncthreads();

    int warp = tid >> 5, lane = tid & 31;
    int n = blockIdx.x * 8 + warp;
    if (n >= NN) return;

    float* st = sStage + warp * 16;
    int t = ntype[n];
    if (lane < 16) st[lane] = x[(size_t)n * 16 + lane] + sNt[t * 16 + lane];
    __syncwarp();

    float acc0 = 0.f, acc1 = 0.f;
#pragma unroll
    for (int k = 0; k < 16; k++) {
        float xk = st[k];
        acc0 = fmaf(xk, sWx[k * 64 + lane], acc0);
        acc1 = fmaf(xk, sWx[k * 64 + lane + 32], acc1);
    }
    g_h[(size_t)n * 64 + lane] = acc0;
    g_h[(size_t)n * 64 + lane + 32] = acc1;

    float pa = acc0 * sAs[lane], pb = acc1 * sAs[lane + 32];
    float qa = acc0 * sAd[lane], qb = acc1 * sAd[lane + 32];
#pragma unroll
    for (int o = 8; o >= 1; o >>= 1) {
        pa += __shfl_xor_sync(0xffffffffu, pa, o);
        pb += __shfl_xor_sync(0xffffffffu, pb, o);
        qa += __shfl_xor_sync(0xffffffffu, qa, o);
        qb += __shfl_xor_sync(0xffffffffu, qb, o);
    }
    if (lane == 0)  { g_ss[n * 4 + 0] = pa; g_ss[n * 4 + 2] = pb; g_sd[n * 4 + 0] = qa; g_sd[n * 4 + 2] = qb; }
    if (lane == 16) { g_ss[n * 4 + 1] = pa; g_ss[n * 4 + 3] = pb; g_sd[n * 4 + 1] = qa; g_sd[n * 4 + 3] = qb; }
}

// ---------------- edge scores (raw, post-leaky), scattered to CSR slots ----------------
template <int LAYER>
__global__ void k_score(const int* __restrict__ ei, const float* __restrict__ eattr,
                        const int* __restrict__ etype) {
    __shared__ float sW[64];
    __shared__ float sT[88];
    const float* wae = (LAYER == 1) ? g_wae1 : g_wae2;
    const float* tae = (LAYER == 1) ? g_tae1 : g_tae2;
    if (threadIdx.x < 64) sW[threadIdx.x] = wae[threadIdx.x];
    if (threadIdx.x < 88) sT[threadIdx.x] = tae[threadIdx.x];
    __syncthreads();

    int e = blockIdx.x * blockDim.x + threadIdx.x;
    if (e >= EE) return;
    int s = ei[e], d = ei[EE + e], t = etype[e];
    float sc[4];
#pragma unroll
    for (int h = 0; h < 4; h++)
        sc[h] = g_ss[s * 4 + h] + g_sd[d * 4 + h] + sT[t * 4 + h];

    const float4* ea = (const float4*)(eattr + (size_t)e * 16);
#pragma unroll
    for (int q = 0; q < 4; q++) {
        float4 a = __ldg(ea + q);
#pragma unroll
        for (int h = 0; h < 4; h++) {
            sc[h] = fmaf(a.x, sW[(4 * q + 0) * 4 + h],
                    fmaf(a.y, sW[(4 * q + 1) * 4 + h],
                    fmaf(a.z, sW[(4 * q + 2) * 4 + h],
                    fmaf(a.w, sW[(4 * q + 3) * 4 + h], sc[h]))));
        }
    }
#pragma unroll
    for (int h = 0; h < 4; h++) sc[h] = (sc[h] > 0.f) ? sc[h] : 0.2f * sc[h];
    int p = __ldg(&g_pos[e]);
    *(float4*)&g_sc[(size_t)p * 4] = make_float4(sc[0], sc[1], sc[2], sc[3]);
}

// ---------------- layer1 aggregation: persistent warps, fused softmax, prefetch ----------------
__global__ void __launch_bounds__(256) k_agg1(const float* __restrict__ eattr,
                                              const float* __restrict__ We, const float* __restrict__ et,
                                              const float* __restrict__ x, const float* __restrict__ res) {
    __shared__ float sEt[22 * 64];
    __shared__ float sWe[16 * 64];
    __shared__ float sRes[16 * 64];
    __shared__ float sWs[8 * 64];
    __shared__ float4 sAl[8][32];
    __shared__ int sS[8][32], sTt[8][32], sE[8][32];
    int tid = threadIdx.x, L = tid & 31, w = tid >> 5;
    for (int i = tid; i < 22 * 64; i += 256) sEt[i] = et[i];
    for (int i = tid; i < 16 * 64; i += 256) { sWe[i] = We[i]; sRes[i] = res[i]; }
    __syncthreads();

    const int H = L >> 3, hb = L >> 4;
    for (int n = blockIdx.x * 8 + w; n < NN; n += gridDim.x * 8) {
        int r0 = __ldg(&g_rowptr[n]), r1 = __ldg(&g_rowptr[n + 1]);

        // fused warp-level online softmax over contiguous CSR scores
        float m[4] = {-3e38f, -3e38f, -3e38f, -3e38f}, dd[4] = {0.f, 0.f, 0.f, 0.f};
        for (int i = r0 + L; i < r1; i += 32) {
            float4 s = *(const float4*)&g_sc[(size_t)i * 4];
            float sv[4] = {s.x, s.y, s.z, s.w};
#pragma unroll
            for (int h = 0; h < 4; h++) {
                if (sv[h] > m[h]) { dd[h] *= __expf(m[h] - sv[h]); m[h] = sv[h]; }
                dd[h] += __expf(sv[h] - m[h]);
            }
        }
#pragma unroll
        for (int o = 16; o >= 1; o >>= 1) {
#pragma unroll
            for (int h = 0; h < 4; h++) {
                float mo = __shfl_xor_sync(0xffffffffu, m[h], o);
                float d_o = __shfl_xor_sync(0xffffffffu, dd[h], o);
                float mn = fmaxf(m[h], mo);
                dd[h] = dd[h] * __expf(m[h] - mn) + d_o * __expf(mo - mn);
                m[h] = mn;
            }
        }
        float inv[4];
#pragma unroll
        for (int h = 0; h < 4; h++) inv[h] = 1.f / (dd[h] + 1e-16f);

        float2 acc = make_float2(0.f, 0.f);
        float w0 = 0.f, w1 = 0.f;
        for (int base = r0; base < r1; base += 32) {
            int nv = min(32, r1 - base);
            if (L < nv) {
                float4 s = *(const float4*)&g_sc[(size_t)(base + L) * 4];
                int2 mt = g_meta[base + L];
                sAl[w][L] = make_float4(__expf(s.x - m[0]) * inv[0], __expf(s.y - m[1]) * inv[1],
                                        __expf(s.z - m[2]) * inv[2], __expf(s.w - m[3]) * inv[3]);
                sS[w][L] = mt.x; sTt[w][L] = mt.y; sE[w][L] = g_eorig[base + L];
            }
            __syncwarp();
            int sj = sS[w][0], tj = sTt[w][0], ej = sE[w][0];
            float2 h2 = *(const float2*)&g_h[(size_t)sj * 64 + 2 * L];
            float ea = __ldg(&eattr[(size_t)ej * 16 + (L & 15)]);
            for (int j = 0; j < nv; j++) {
                float4 al = sAl[w][j];
                float2 ev = *(const float2*)&sEt[tj * 64 + 2 * L];
                float ah = (H == 0) ? al.x : ((H == 1) ? al.y : ((H == 2) ? al.z : al.w));
                acc.x = fmaf(ah, h2.x + ev.x, acc.x);
                acc.y = fmaf(ah, h2.y + ev.y, acc.y);
                float aw0 = hb ? al.y : al.x, aw1 = hb ? al.w : al.z;
                w0 = fmaf(aw0, ea, w0);
                w1 = fmaf(aw1, ea, w1);
                if (j + 1 < nv) {
                    sj = sS[w][j + 1]; tj = sTt[w][j + 1]; ej = sE[w][j + 1];
                    h2 = *(const float2*)&g_h[(size_t)sj * 64 + 2 * L];
                    ea = __ldg(&eattr[(size_t)ej * 16 + (L & 15)]);
                }
            }
            __syncwarp();
        }
        sWs[w * 64 + L] = w0;
        sWs[w * 64 + 32 + L] = w1;
        __syncwarp();
#pragma unroll
        for (int k = 0; k < 16; k++) {
            float wk = sWs[w * 64 + H * 16 + k];
            float2 we = *(const float2*)&sWe[k * 64 + 2 * L];
            acc.x = fmaf(wk, we.x, acc.x);
            acc.y = fmaf(wk, we.y, acc.y);
        }
        const float4* xp = (const float4*)(x + (size_t)n * 16);
        float4 xa = __ldg(xp), xb = __ldg(xp + 1), xc = __ldg(xp + 2), xd = __ldg(xp + 3);
        float xv[16] = {xa.x, xa.y, xa.z, xa.w, xb.x, xb.y, xb.z, xb.w,
                        xc.x, xc.y, xc.z, xc.w, xd.x, xd.y, xd.z, xd.w};
#pragma unroll
        for (int k = 0; k < 16; k++) {
            float2 rv = *(const float2*)&sRes[k * 64 + 2 * L];
            acc.x = fmaf(xv[k], rv.x, acc.x);
            acc.y = fmaf(xv[k], rv.y, acc.y);
        }
        g_z1[(size_t)n * 64 + 2 * L]     = fmaxf(acc.x, 0.f);
        g_z1[(size_t)n * 64 + 2 * L + 1] = fmaxf(acc.y, 0.f);
        __syncwarp();
    }
}

// ---------------- layer2 projection: tiled GEMM + fused ss/sd ----------------
__global__ void __launch_bounds__(256) k_proj2(const int* __restrict__ ntype, const float* __restrict__ nt,
                                               const float* __restrict__ Wx,
                                               const float* __restrict__ a_s, const float* __restrict__ a_d) {
    extern __shared__ float sm[];
    float* sA = sm;              // 128*68
    float* sB = sA + 128 * 68;   // 64*64
    float* sNt = sB + 4096;      // 8*64
    float* sAs = sNt + 512;      // 64
    float* sAd = sAs + 64;       // 64
    int*   sTy = (int*)(sAd + 64); // 128

    int tid = threadIdx.x;
    int by = blockIdx.y;
    int rbase = blockIdx.x * 128;

    for (int i = tid; i < 512; i += 256) sNt[i] = nt[i];
    if (tid < 64) { sAs[tid] = a_s[by * 64 + tid]; sAd[tid] = a_d[by * 64 + tid]; }
    if (tid < 128) { int r = rbase + tid; sTy[tid] = (r < NN) ? ntype[r] : 0; }
    __syncthreads();

    for (int i = tid; i < 1024; i += 256) {
        int k = i >> 4, cg = i & 15;
        float4 v = *(const float4*)&Wx[(size_t)k * 256 + by * 64 + cg * 4];
        *(float4*)&sB[k * 64 + cg * 4] = v;
    }
    for (int i = tid; i < 2048; i += 256) {
        int r = i >> 4, sg = i & 15;
        int gr = rbase + r;
        float4 v = make_float4(0.f, 0.f, 0.f, 0.f);
        if (gr < NN) {
            v = *(const float4*)&g_z1[(size_t)gr * 64 + sg * 4];
            float4 nv = *(const float4*)&sNt[sTy[r] * 64 + sg * 4];
            v.x += nv.x; v.y += nv.y; v.z += nv.z; v.w += nv.w;
        }
        *(float4*)&sA[r * 68 + sg * 4] = v;
    }
    __syncthreads();

    int tx = tid & 15, ty = tid >> 4;
    int c0 = tx * 4, r0 = ty * 8;
    float4 acc[8];
#pragma unroll
    for (int i = 0; i < 8; i++) acc[i] = make_float4(0.f, 0.f, 0.f, 0.f);

#pragma unroll 4
    for (int k = 0; k < 64; k++) {
        float4 b = *(const float4*)&sB[k * 64 + c0];
#pragma unroll
        for (int i = 0; i < 8; i++) {
            float a = sA[(r0 + i) * 68 + k];
            acc[i].x = fmaf(a, b.x, acc[i].x);
            acc[i].y = fmaf(a, b.y, acc[i].y);
            acc[i].z = fmaf(a, b.z, acc[i].z);
            acc[i].w = fmaf(a, b.w, acc[i].w);
        }
    }

    float ps[8], pd[8];
#pragma unroll
    for (int i = 0; i < 8; i++) {
        int gr = rbase + r0 + i;
        if (gr < NN) *(float4*)&g_h[(size_t)gr * 256 + by * 64 + c0] = acc[i];
        ps[i] = acc[i].x * sAs[c0] + acc[i].y * sAs[c0 + 1] + acc[i].z * sAs[c0 + 2] + acc[i].w * sAs[c0 + 3];
        pd[i] = acc[i].x * sAd[c0] + acc[i].y * sAd[c0 + 1] + acc[i].z * sAd[c0 + 2] + acc[i].w * sAd[c0 + 3];
    }
#pragma unroll
    for (int o = 1; o < 16; o <<= 1) {
#pragma unroll
        for (int i = 0; i < 8; i++) {
            ps[i] += __shfl_xor_sync(0xffffffffu, ps[i], o);
            pd[i] += __shfl_xor_sync(0xffffffffu, pd[i], o);
        }
    }
    if (tx == 0) {
#pragma unroll
        for (int i = 0; i < 8; i++) {
            int gr = rbase + r0 + i;
            if (gr < NN) { g_ss[gr * 4 + by] = ps[i]; g_sd[gr * 4 + by] = pd[i]; }
        }
    }
}

// ---------------- layer2 aggregation: persistent warps, fused softmax, prefetch ----------------
__global__ void __launch_bounds__(256) k_agg2(const float* __restrict__ eattr,
                                              const float* __restrict__ We, const float* __restrict__ et,
                                              float* __restrict__ zout) {
    __shared__ float4 sEt[22 * 64];
    __shared__ float4 sWe[16 * 64];
    __shared__ float  sWs[8 * 64];
    __shared__ float4 sAl[8][32];
    __shared__ int sS[8][32], sTt[8][32], sE[8][32];
    int tid = threadIdx.x, L = tid & 31, w = tid >> 5;
    for (int i = tid; i < 22 * 64; i += 256) sEt[i] = *(const float4*)&et[(size_t)i * 4];
    for (int i = tid; i < 16 * 64; i += 256) sWe[i] = *(const float4*)&We[(size_t)i * 4];
    __syncthreads();

    const int hb = L >> 4;
    for (int n = blockIdx.x * 8 + w; n < NN; n += gridDim.x * 8) {
        int r0 = __ldg(&g_rowptr[n]), r1 = __ldg(&g_rowptr[n + 1]);

        float m[4] = {-3e38f, -3e38f, -3e38f, -3e38f}, dd[4] = {0.f, 0.f, 0.f, 0.f};
        for (int i = r0 + L; i < r1; i += 32) {
            float4 s = *(const float4*)&g_sc[(size_t)i * 4];
            float sv[4] = {s.x, s.y, s.z, s.w};
#pragma unroll
            for (int h = 0; h < 4; h++) {
                if (sv[h] > m[h]) { dd[h] *= __expf(m[h] - sv[h]); m[h] = sv[h]; }
                dd[h] += __expf(sv[h] - m[h]);
            }
        }
#pragma unroll
        for (int o = 16; o >= 1; o >>= 1) {
#pragma unroll
            for (int h = 0; h < 4; h++) {
                float mo = __shfl_xor_sync(0xffffffffu, m[h], o);
                float d_o = __shfl_xor_sync(0xffffffffu, dd[h], o);
                float mn = fmaxf(m[h], mo);
                dd[h] = dd[h] * __expf(m[h] - mn) + d_o * __expf(mo - mn);
                m[h] = mn;
            }
        }
        float inv[4];
#pragma unroll
        for (int h = 0; h < 4; h++) inv[h] = 1.f / (dd[h] + 1e-16f);

        float4 acc0 = make_float4(0.f, 0.f, 0.f, 0.f);
        float4 acc1 = make_float4(0.f, 0.f, 0.f, 0.f);
        float w0 = 0.f, w1 = 0.f;

        for (int base = r0; base < r1; base += 32) {
            int nv = min(32, r1 - base);
            if (L < nv) {
                float4 s = *(const float4*)&g_sc[(size_t)(base + L) * 4];
                int2 mt = g_meta[base + L];
                sAl[w][L] = make_float4(__expf(s.x - m[0]) * inv[0], __expf(s.y - m[1]) * inv[1],
                                        __expf(s.z - m[2]) * inv[2], __expf(s.w - m[3]) * inv[3]);
                sS[w][L] = mt.x; sTt[w][L] = mt.y; sE[w][L] = g_eorig[base + L];
            }
            __syncwarp();
            int sj = sS[w][0], tj = sTt[w][0], ej = sE[w][0];
            const float4* hp = (const float4*)(g_h + (size_t)sj * 256);
            float4 h0 = __ldg(hp + L);
            float4 h1 = __ldg(hp + 32 + L);
            float ea = __ldg(&eattr[(size_t)ej * 16 + (L & 15)]);
            for (int j = 0; j < nv; j++) {
                float4 al = sAl[w][j];
                float4 e0 = sEt[tj * 64 + L];
                float4 e1 = sEt[tj * 64 + 32 + L];
                float aA = hb ? al.y : al.x;
                float aB = hb ? al.w : al.z;
                acc0.x = fmaf(aA, h0.x + e0.x, acc0.x);
                acc0.y = fmaf(aA, h0.y + e0.y, acc0.y);
                acc0.z = fmaf(aA, h0.z + e0.z, acc0.z);
                acc0.w = fmaf(aA, h0.w + e0.w, acc0.w);
                acc1.x = fmaf(aB, h1.x + e1.x, acc1.x);
                acc1.y = fmaf(aB, h1.y + e1.y, acc1.y);
                acc1.z = fmaf(aB, h1.z + e1.z, acc1.z);
                acc1.w = fmaf(aB, h1.w + e1.w, acc1.w);
                w0 = fmaf(aA, ea, w0);
                w1 = fmaf(aB, ea, w1);
                if (j + 1 < nv) {
                    sj = sS[w][j + 1]; tj = sTt[w][j + 1]; ej = sE[w][j + 1];
                    const float4* hp2 = (const float4*)(g_h + (size_t)sj * 256);
                    h0 = __ldg(hp2 + L);
                    h1 = __ldg(hp2 + 32 + L);
                    ea = __ldg(&eattr[(size_t)ej * 16 + (L & 15)]);
                }
            }
            __syncwarp();
        }
        sWs[w * 64 + L] = w0;
        sWs[w * 64 + 32 + L] = w1;
        __syncwarp();

        const int H0 = hb, H1 = 2 + hb;
#pragma unroll
        for (int k = 0; k < 16; k++) {
            float k0 = sWs[w * 64 + H0 * 16 + k];
            float k1 = sWs[w * 64 + H1 * 16 + k];
            float4 we0 = sWe[k * 64 + L];
            float4 we1 = sWe[k * 64 + 32 + L];
            acc0.x = fmaf(k0, we0.x, acc0.x); acc0.y = fmaf(k0, we0.y, acc0.y);
            acc0.z = fmaf(k0, we0.z, acc0.z); acc0.w = fmaf(k0, we0.w, acc0.w);
            acc1.x = fmaf(k1, we1.x, acc1.x); acc1.y = fmaf(k1, we1.y, acc1.y);
            acc1.z = fmaf(k1, we1.z, acc1.z); acc1.w = fmaf(k1, we1.w, acc1.w);
        }
        float4 sm4;
        sm4.x = acc0.x + acc1.x; sm4.y = acc0.y + acc1.y;
        sm4.z = acc0.z + acc1.z; sm4.w = acc0.w + acc1.w;
        sm4.x += __shfl_xor_sync(0xffffffffu, sm4.x, 16);
        sm4.y += __shfl_xor_sync(0xffffffffu, sm4.y, 16);
        sm4.z += __shfl_xor_sync(0xffffffffu, sm4.z, 16);
        sm4.w += __shfl_xor_sync(0xffffffffu, sm4.w, 16);
        if (L < 16) {
            float4 z1v = *(const float4*)&g_z1[(size_t)n * 64 + 4 * L];
            float4 o;
            o.x = z1v.x + 0.25f * sm4.x;
            o.y = z1v.y + 0.25f * sm4.y;
            o.z = z1v.z + 0.25f * sm4.z;
            o.w = z1v.w + 0.25f * sm4.w;
            *(float4*)&zout[(size_t)n * 64 + 4 * L] = o;
        }
        __syncwarp();
    }
}

// ---------------- decoder: persistent tiled GEMM, W1 loaded once per block ----------------
__global__ void __launch_bounds__(256) k_dec(const int* __restrict__ eli, const float* __restrict__ z,
                                             const float* __restrict__ W1, const float* __restrict__ b1,
                                             const float* __restrict__ W2, const float* __restrict__ b2,
                                             float* __restrict__ pred) {
    extern __shared__ float sm[];
    float* sA = sm;                 // 64*132
    float* sB = sA + 64 * 132;      // 128*64
    int*   sR = (int*)(sB + 8192);  // 64
    int*   sC = sR + 64;            // 64
    float* sb1 = (float*)(sC + 64); // 64
    float* sw2 = sb1 + 64;          // 64

    int tid = threadIdx.x;
    if (tid < 64) { sb1[tid] = b1[tid]; sw2[tid] = W2[tid]; }
    for (int i = tid; i < 2048; i += 256)
        *(float4*)&sB[i * 4] = *(const float4*)&W1[(size_t)i * 4];

    int tx = tid & 15, ty = tid >> 4;
    int c0 = tx * 4, r0 = ty * 4;
    float bb = __ldg(&b2[0]);

    const int NT = ELN / 64;
    for (int tile = blockIdx.x; tile < NT; tile += gridDim.x) {
        int ebase = tile * 64;
        __syncthreads();
        if (tid < 64) sR[tid] = __ldg(&eli[ebase + tid]);
        else if (tid < 128) sC[tid - 64] = __ldg(&eli[ELN + ebase + tid - 64]);
        __syncthreads();
        for (int i = tid; i < 2048; i += 256) {
            int e = i >> 5, sg = i & 31;
            int node = (sg < 16) ? sR[e] : sC[e];
            float4 v = *(const float4*)&z[(size_t)node * 64 + (sg & 15) * 4];
            *(float4*)&sA[e * 132 + sg * 4] = v;
        }
        __syncthreads();

        float4 acc[4];
#pragma unroll
        for (int i = 0; i < 4; i++) acc[i] = make_float4(0.f, 0.f, 0.f, 0.f);

#pragma unroll 4
        for (int k = 0; k < 128; k++) {
            float4 b = *(const float4*)&sB[k * 64 + c0];
#pragma unroll
            for (int i = 0; i < 4; i++) {
                float a = sA[(r0 + i) * 132 + k];
                acc[i].x = fmaf(a, b.x, acc[i].x);
                acc[i].y = fmaf(a, b.y, acc[i].y);
                acc[i].z = fmaf(a, b.z, acc[i].z);
                acc[i].w = fmaf(a, b.w, acc[i].w);
            }
        }

        float p[4];
#pragma unroll
        for (int i = 0; i < 4; i++) {
            float hx = fmaxf(acc[i].x + sb1[c0],     0.f);
            float hy = fmaxf(acc[i].y + sb1[c0 + 1], 0.f);
            float hz = fmaxf(acc[i].z + sb1[c0 + 2], 0.f);
            float hw = fmaxf(acc[i].w + sb1[c0 + 3], 0.f);
            p[i] = hx * sw2[c0] + hy * sw2[c0 + 1] + hz * sw2[c0 + 2] + hw * sw2[c0 + 3];
        }
#pragma unroll
        for (int o = 1; o < 16; o <<= 1) {
#pragma unroll
            for (int i = 0; i < 4; i++) p[i] += __shfl_xor_sync(0xffffffffu, p[i], o);
        }
        if (tx == 0) {
#pragma unroll
            for (int i = 0; i < 4; i++) pred[ebase + r0 + i] = p[i] + bb;
        }
    }
}

// ---------------- launch ----------------
extern "C" void kernel_launch(void* const* d_in, const int* in_sizes, int n_in,
                              void* d_out, int out_size) {
    const float* x     = (const float*)d_in[0];
    const int*   ei    = (const int*)d_in[1];
    const int*   ntype = (const int*)d_in[2];
    const float* eattr = (const float*)d_in[3];
    const int*   etype = (const int*)d_in[4];
    const int*   eli   = (const int*)d_in[5];
    const float* Wx1   = (const float*)d_in[6];
    const float* We1   = (const float*)d_in[7];
    const float* nt1   = (const float*)d_in[8];
    const float* et1   = (const float*)d_in[9];
    const float* as1   = (const float*)d_in[10];
    const float* ad1   = (const float*)d_in[11];
    const float* ae1   = (const float*)d_in[12];
    const float* res1  = (const float*)d_in[13];
    const float* Wx2   = (const float*)d_in[14];
    const float* We2   = (const float*)d_in[15];
    const float* nt2   = (const float*)d_in[16];
    const float* et2   = (const float*)d_in[17];
    const float* as2   = (const float*)d_in[18];
    const float* ad2   = (const float*)d_in[19];
    const float* ae2   = (const float*)d_in[20];
    const float* W1    = (const float*)d_in[21];
    const float* b1    = (const float*)d_in[22];
    const float* W2    = (const float*)d_in[23];
    const float* b2    = (const float*)d_in[24];

    float* pred = (float*)d_out;
    float* zout = pred + ELN;

    // CSR build
    k_zero_cnt<<<(NN + 255) / 256, 256>>>();
    k_count<<<(EE + 255) / 256, 256>>>(ei);
    k_scanfuse<<<1, 1024>>>(We1, ae1, et1, We2, ae2, et2);
    k_fill<<<(EE + 255) / 256, 256>>>(ei, etype);

    // layer 1
    k_proj1<<<(NN + 7) / 8, 256>>>(x, ntype, nt1, Wx1, as1, ad1);
    k_score<1><<<(EE + 255) / 256, 256>>>(ei, eattr, etype);
    k_agg1<<<1184, 256>>>(eattr, We1, et1, x, res1);

    // layer 2
    size_t smP2 = (size_t)(128 * 68 + 64 * 64 + 512 + 64 + 64 + 128) * sizeof(float);
    cudaFuncSetAttribute((const void*)k_proj2, cudaFuncAttributeMaxDynamicSharedMemorySize, (int)smP2);
    k_proj2<<<dim3((NN + 127) / 128, 4), 256, smP2>>>(ntype, nt2, Wx2, as2, ad2);
    k_score<2><<<(EE + 255) / 256, 256>>>(ei, eattr, etype);
    k_agg2<<<1184, 256>>>(eattr, We2, et2, zout);

    // decoder
    size_t smD = (size_t)(64 * 132 + 128 * 64 + 64 + 64 + 64 + 64) * sizeof(float);
    cudaFuncSetAttribute((const void*)k_dec, cudaFuncAttributeMaxDynamicSharedMemorySize, (int)smD);
    k_dec<<<592, 256, smD>>>(eli, zout, W1, b1, W2, b2, pred);
}